// round 5
// baseline (speedup 1.0000x reference)
#include <cuda_runtime.h>
#include <math.h>

#define N_ 8192
#define K_ 64
#define CARDN 64
#define BIGF 1e9f
#define EPSV 0.01f
#define INV_EPS 100.0f
#define LOG64 4.1588830833596715f
#define SINK_ITERS 300

// ---------------- device scratch (no allocations allowed) ----------------
__device__ float g_T[N_ * K_];      // adj @ S   [8192,64]
__device__ float g_C[K_ * K_];      // S^T (adj S) [64,64]
__device__ float g_dgm0[CARDN * 2];
__device__ float g_dgm1[CARDN * 2];
__device__ float g_loss[4];

// ---------------- packed fp32x2 helpers (Blackwell fp32 2x pipe) ----------------
#define PACK2(out, lo, hi) \
    asm("mov.b64 %0, {%1, %2};" : "=l"(out) : "r"(__float_as_uint(lo)), "r"(__float_as_uint(hi)))
#define FMA2(d, a, b) \
    asm("fma.rn.f32x2 %0, %1, %2, %0;" : "+l"(d) : "l"(a), "l"(b))
#define UNPACK2(lo, hi, in) do { \
    unsigned _ulo, _uhi; \
    asm("mov.b64 {%0, %1}, %2;" : "=r"(_ulo), "=r"(_uhi) : "l"(in)); \
    lo = __uint_as_float(_ulo); hi = __uint_as_float(_uhi); } while (0)

// ================= GEMM1: T = adj @ S  (8192x8192 * 8192x64) =================
// 128 blocks x 256 threads; BM=64, BN=64, BK=32.
// A stored to smem PRE-SPLATTED: As2[k][2m] = As2[k][2m+1] = A[m][k], so the
// inner loop reads (a,a) 64-bit pairs directly (no per-kk register splats).
// Double-buffered smem (exactly 48KB static), register prefetch, 1 barrier/tile.
__global__ void __launch_bounds__(256) gemm1_kernel(const float* __restrict__ A,
                                                    const float* __restrict__ S) {
    __shared__ float As2[2][32][128];   // 32 KB
    __shared__ float Bs[2][32][64];     // 16 KB
    int tid = threadIdx.x;
    int m0 = blockIdx.x * 64;
    int tx = tid & 15, ty = tid >> 4;

    // loader indices
    int mA = tid >> 3;          // 0..31  (second load covers +32)
    int kqA = tid & 7;          // float4 along k
    int krB = tid >> 4;         // 0..15  (second load covers +16)
    int nqB = tid & 15;

    unsigned long long acc[4][2];
#pragma unroll
    for (int r = 0; r < 4; r++) { acc[r][0] = 0ull; acc[r][1] = 0ull; }

    const float* Arow0 = A + (size_t)(m0 + mA) * N_ + kqA * 4;
    const float* Arow1 = A + (size_t)(m0 + mA + 32) * N_ + kqA * 4;

    // prologue: load tile 0 into buffer 0
    {
        float4 a0 = *(const float4*)(Arow0);
        float4 a1 = *(const float4*)(Arow1);
        float4 b0 = *(const float4*)(S + (size_t)(krB) * 64 + nqB * 4);
        float4 b1 = *(const float4*)(S + (size_t)(krB + 16) * 64 + nqB * 4);
#pragma unroll
        for (int c = 0; c < 4; c++) {
            float v0 = ((const float*)&a0)[c];
            float v1 = ((const float*)&a1)[c];
            *(float2*)&As2[0][kqA * 4 + c][2 * mA] = make_float2(v0, v0);
            *(float2*)&As2[0][kqA * 4 + c][2 * (mA + 32)] = make_float2(v1, v1);
        }
        *(float4*)&Bs[0][krB][nqB * 4] = b0;
        *(float4*)&Bs[0][krB + 16][nqB * 4] = b1;
    }
    __syncthreads();

    for (int k0i = 0; k0i < 256; k0i++) {
        int buf = k0i & 1;
        float4 na0, na1, nb0, nb1;
        bool more = (k0i < 255);
        if (more) {
            int k0n = (k0i + 1) * 32;
            na0 = *(const float4*)(Arow0 + k0n);
            na1 = *(const float4*)(Arow1 + k0n);
            nb0 = *(const float4*)(S + (size_t)(k0n + krB) * 64 + nqB * 4);
            nb1 = *(const float4*)(S + (size_t)(k0n + krB + 16) * 64 + nqB * 4);
        }
#pragma unroll
        for (int kk = 0; kk < 32; kk++) {
            ulonglong2 aL = *(const ulonglong2*)&As2[buf][kk][ty * 8];
            ulonglong2 aH = *(const ulonglong2*)&As2[buf][kk][ty * 8 + 4];
            float4 bv = *(const float4*)&Bs[buf][kk][tx * 4];
            unsigned long long b01, b23;
            PACK2(b01, bv.x, bv.y);
            PACK2(b23, bv.z, bv.w);
            FMA2(acc[0][0], aL.x, b01); FMA2(acc[0][1], aL.x, b23);
            FMA2(acc[1][0], aL.y, b01); FMA2(acc[1][1], aL.y, b23);
            FMA2(acc[2][0], aH.x, b01); FMA2(acc[2][1], aH.x, b23);
            FMA2(acc[3][0], aH.y, b01); FMA2(acc[3][1], aH.y, b23);
        }
        if (more) {
            int nb = buf ^ 1;
#pragma unroll
            for (int c = 0; c < 4; c++) {
                float v0 = ((const float*)&na0)[c];
                float v1 = ((const float*)&na1)[c];
                *(float2*)&As2[nb][kqA * 4 + c][2 * mA] = make_float2(v0, v0);
                *(float2*)&As2[nb][kqA * 4 + c][2 * (mA + 32)] = make_float2(v1, v1);
            }
            *(float4*)&Bs[nb][krB][nqB * 4] = nb0;
            *(float4*)&Bs[nb][krB + 16][nqB * 4] = nb1;
        }
        __syncthreads();
    }
#pragma unroll
    for (int r = 0; r < 4; r++) {
        float o0, o1, o2, o3;
        UNPACK2(o0, o1, acc[r][0]);
        UNPACK2(o2, o3, acc[r][1]);
        *(float4*)&g_T[(size_t)(m0 + ty * 4 + r) * 64 + tx * 4] = make_float4(o0, o1, o2, o3);
    }
}

// ================= GEMM2: C = S^T @ T  (64x8192 * 8192x64) =================
// 64 blocks (one output row each); vectorized float4 loads of T (L2-resident).
__global__ void __launch_bounds__(256) gemm2_kernel(const float* __restrict__ S) {
    int b = blockIdx.x;
    int tid = threadIdx.x;
    int j4 = (tid & 15) * 4;
    int slice = tid >> 4;   // 16 slices
    float4 acc = make_float4(0.f, 0.f, 0.f, 0.f);
    for (int k = slice; k < N_; k += 16) {
        float sb = __ldg(S + (size_t)k * 64 + b);
        float4 tv = *(const float4*)&g_T[(size_t)k * 64 + j4];
        acc.x += sb * tv.x; acc.y += sb * tv.y;
        acc.z += sb * tv.z; acc.w += sb * tv.w;
    }
    __shared__ float4 red[256];
    red[tid] = acc;
    __syncthreads();
    if (tid < 64) {
        int g = tid >> 2, comp = tid & 3;
        float v = 0.f;
#pragma unroll
        for (int sl = 0; sl < 16; sl++)
            v += ((const float*)&red[sl * 16 + g])[comp];
        g_C[b * 64 + tid] = v;
    }
}

// ========== finalize D + Prim MST + dgm0 + triangle deaths + top-64 dgm1 ==========
__global__ void __launch_bounds__(1024) topo_kernel() {
    __shared__ float Dsm[64][65];
    __shared__ float pers[4096];
    __shared__ float wred[32];
    __shared__ float ws_s[63];
    __shared__ int us_s[63], vs_s[63];
    __shared__ float mind[64];
    __shared__ int minu[64];
    __shared__ unsigned long long msk[64];
    __shared__ float mx_s;
    __shared__ float bv_s[32];
    __shared__ int bi_s[32];

    int tid = threadIdx.x;
    int lane = tid & 31, warp = tid >> 5;

    // 1) symmetrize + global max
    float lmax = -1e30f;
#pragma unroll
    for (int w = 0; w < 4; w++) {
        int p = tid + w * 1024;
        int i = p >> 6, jj = p & 63;
        float cs = 0.5f * (g_C[i * 64 + jj] + g_C[jj * 64 + i]);
        Dsm[i][jj] = cs;
        lmax = fmaxf(lmax, cs);
    }
    for (int o = 16; o; o >>= 1) lmax = fmaxf(lmax, __shfl_xor_sync(~0u, lmax, o));
    if (lane == 0) wred[warp] = lmax;
    __syncthreads();
    if (warp == 0) {
        float v = wred[lane];
        for (int o = 16; o; o >>= 1) v = fmaxf(v, __shfl_xor_sync(~0u, v, o));
        if (lane == 0) mx_s = v;
    }
    __syncthreads();
    float inv = 1.0f / (mx_s + 1e-12f);
#pragma unroll
    for (int w = 0; w < 4; w++) {
        int p = tid + w * 1024;
        int i = p >> 6, jj = p & 63;
        float d = 1.0f - Dsm[i][jj] * inv;
        Dsm[i][jj] = (i == jj) ? 0.0f : d;
    }
    __syncthreads();

    // 2) Prim MST on warp 0 (63 sequential steps)
    if (warp == 0) {
        unsigned long long intree = 1ull;
#pragma unroll
        for (int h = 0; h < 2; h++) {
            int v = lane + 32 * h;
            mind[v] = Dsm[0][v];
            minu[v] = 0;
        }
        __syncwarp();
        for (int step = 0; step < 63; step++) {
            float bval = BIGF; int bidx = 64;
#pragma unroll
            for (int h = 0; h < 2; h++) {
                int v = lane + 32 * h;
                float mv = ((intree >> v) & 1ull) ? BIGF : mind[v];
                if (mv < bval || (mv == bval && v < bidx)) { bval = mv; bidx = v; }
            }
            for (int o = 16; o; o >>= 1) {
                float ov = __shfl_xor_sync(~0u, bval, o);
                int oi = __shfl_xor_sync(~0u, bidx, o);
                if (ov < bval || (ov == bval && oi < bidx)) { bval = ov; bidx = oi; }
            }
            int vstar = bidx;
            if (lane == 0) { ws_s[step] = bval; us_s[step] = minu[vstar]; vs_s[step] = vstar; }
            intree |= (1ull << vstar);
#pragma unroll
            for (int h = 0; h < 2; h++) {
                int v = lane + 32 * h;
                float dv = Dsm[vstar][v];
                if (dv < mind[v]) { mind[v] = dv; minu[v] = vstar; }
            }
            __syncwarp();
        }
    }
    __syncthreads();

    // 3) dgm0 (order irrelevant for W1) + MST mask
    if (tid < 64) {
        g_dgm0[2 * tid] = 0.0f;
        g_dgm0[2 * tid + 1] = (tid < 63) ? ws_s[tid] : 0.0f;
        msk[tid] = 0ull;
    }
    __syncthreads();
    if (tid < 63) {
        atomicOr(&msk[us_s[tid]], 1ull << vs_s[tid]);
        atomicOr(&msk[vs_s[tid]], 1ull << us_s[tid]);
    }
    __syncthreads();

    // 4) persistence of 1-cycles: death = max(Dij, min_{k!=i,j} max(Dik, Djk))
#pragma unroll
    for (int w = 0; w < 4; w++) {
        int p = tid + w * 1024;
        int i = p >> 6, jj = p & 63;
        float pe = -1.0f;
        if (i < jj && !((msk[i] >> jj) & 1ull)) {
            float mm = BIGF;
#pragma unroll
            for (int k = 0; k < 64; k++) {
                float t = fmaxf(Dsm[i][k], Dsm[jj][k]);
                if (k != i && k != jj) mm = fminf(mm, t);
            }
            float dij = Dsm[i][jj];
            pe = fmaxf(dij, mm) - dij;
        }
        pers[p] = pe;
    }
    __syncthreads();

    // 5) top-64 by (pers, lowest flat index) -> dgm1
    for (int r = 0; r < 64; r++) {
        float bval = -3e9f; int bidx = 1 << 30;
#pragma unroll
        for (int w = 0; w < 4; w++) {
            int p = tid + w * 1024;
            float v = pers[p];
            if (v > bval || (v == bval && p < bidx)) { bval = v; bidx = p; }
        }
        for (int o = 16; o; o >>= 1) {
            float ov = __shfl_xor_sync(~0u, bval, o);
            int oi = __shfl_xor_sync(~0u, bidx, o);
            if (ov > bval || (ov == bval && oi < bidx)) { bval = ov; bidx = oi; }
        }
        if (lane == 0) { bv_s[warp] = bval; bi_s[warp] = bidx; }
        __syncthreads();
        if (warp == 0) {
            float v2 = bv_s[lane]; int i2 = bi_s[lane];
            for (int o = 16; o; o >>= 1) {
                float ov = __shfl_xor_sync(~0u, v2, o);
                int oi = __shfl_xor_sync(~0u, i2, o);
                if (ov > v2 || (ov == v2 && oi < i2)) { v2 = ov; i2 = oi; }
            }
            if (lane == 0) {
                int i = i2 >> 6, jj = i2 & 63;
                float b = 0.f, d = 0.f;
                if (v2 > 0.f) { b = Dsm[i][jj]; d = b + v2; }
                g_dgm1[2 * r] = b;
                g_dgm1[2 * r + 1] = d;
                pers[i2] = -4e9f;  // remove from future rounds
            }
        }
        __syncthreads();
    }
}

// ================= Sinkhorn W1: 2 blocks, 2 interleaved chains each =================
// Chain 0 of a block uses X=dgm0, chain 1 uses X=dgm1 (with the block's Y pair).
// 8 threads per row (544 threads, 17 warps); the two chains' dependent latency
// chains (LDS -> MUFU -> SHFL) interleave in the issue stream.
__global__ void __launch_bounds__(544) sinkhorn_kernel(const float* __restrict__ Yb0,
                                                       const float* __restrict__ Yb1,
                                                       const float* __restrict__ Yn0,
                                                       const float* __restrict__ Yn1) {
    __shared__ float Cm[2][65][66];
    __shared__ float fsh[2][65], gsh[2][65];
    __shared__ float rsum[2][17];

    int blk = blockIdx.x;
    const float* Ya = blk ? Yn0 : Yb0;   // pairs with dgm0
    const float* Yb = blk ? Yn1 : Yb1;   // pairs with dgm1
    int t = threadIdx.x;

    for (int idx = t; idx < 65 * 65; idx += 544) {
        int i = idx / 65, j = idx % 65;
        float v0, v1;
        if (i < 64 && j < 64) {
            v0 = fmaxf(fabsf(g_dgm0[2 * i] - Ya[2 * j]),
                       fabsf(g_dgm0[2 * i + 1] - Ya[2 * j + 1]));
            v1 = fmaxf(fabsf(g_dgm1[2 * i] - Yb[2 * j]),
                       fabsf(g_dgm1[2 * i + 1] - Yb[2 * j + 1]));
        } else if (i < 64) {
            v0 = 0.5f * (g_dgm0[2 * i + 1] - g_dgm0[2 * i]);
            v1 = 0.5f * (g_dgm1[2 * i + 1] - g_dgm1[2 * i]);
        } else if (j < 64) {
            v0 = 0.5f * (Ya[2 * j + 1] - Ya[2 * j]);
            v1 = 0.5f * (Yb[2 * j + 1] - Yb[2 * j]);
        } else {
            v0 = 0.f; v1 = 0.f;
        }
        Cm[0][i][j] = v0;
        Cm[1][i][j] = v1;
    }
    if (t < 65) { fsh[0][t] = 0.f; fsh[1][t] = 0.f; gsh[0][t] = 0.f; gsh[1][t] = 0.f; }
    __syncthreads();

    int row = t >> 3; if (row > 64) row = 64;
    int sub = t & 7;
    bool lead = (t < 520) && (sub == 0);
    float la = (row == 64) ? LOG64 : 0.f;

    for (int it = 0; it < SINK_ITERS; it++) {
        // f[i] = eps*(loga - LSE_j((g[j]-C[i,j])/eps))   -- rows contiguous
        {
            float xs0[9], xs1[9], m0 = -1e30f, m1 = -1e30f;
#pragma unroll
            for (int s2 = 0; s2 < 9; s2++) {
                int j = sub + 8 * s2;
                bool ok = (j < 65);
                float x0 = ok ? (gsh[0][j] - Cm[0][row][j]) * INV_EPS : -1e38f;
                float x1 = ok ? (gsh[1][j] - Cm[1][row][j]) * INV_EPS : -1e38f;
                xs0[s2] = x0; xs1[s2] = x1;
                m0 = fmaxf(m0, x0); m1 = fmaxf(m1, x1);
            }
            float s0 = 0.f, s1 = 0.f;
#pragma unroll
            for (int s2 = 0; s2 < 9; s2++) {
                s0 += __expf(xs0[s2] - m0);
                s1 += __expf(xs1[s2] - m1);
            }
#pragma unroll
            for (int o = 1; o < 8; o <<= 1) {
                float om0 = __shfl_xor_sync(~0u, m0, o), os0 = __shfl_xor_sync(~0u, s0, o);
                float om1 = __shfl_xor_sync(~0u, m1, o), os1 = __shfl_xor_sync(~0u, s1, o);
                float nm0 = fmaxf(m0, om0);
                s0 = s0 * __expf(m0 - nm0) + os0 * __expf(om0 - nm0); m0 = nm0;
                float nm1 = fmaxf(m1, om1);
                s1 = s1 * __expf(m1 - nm1) + os1 * __expf(om1 - nm1); m1 = nm1;
            }
            if (lead) {
                fsh[0][row] = EPSV * (la - (m0 + __logf(s0)));
                fsh[1][row] = EPSV * (la - (m1 + __logf(s1)));
            }
        }
        __syncthreads();
        // g[j] = eps*(logb - LSE_i((f[i]-C[i,j])/eps))   -- strided column read
        {
            float xs0[9], xs1[9], m0 = -1e30f, m1 = -1e30f;
#pragma unroll
            for (int s2 = 0; s2 < 9; s2++) {
                int i = sub + 8 * s2;
                bool ok = (i < 65);
                float x0 = ok ? (fsh[0][i] - Cm[0][i][row]) * INV_EPS : -1e38f;
                float x1 = ok ? (fsh[1][i] - Cm[1][i][row]) * INV_EPS : -1e38f;
                xs0[s2] = x0; xs1[s2] = x1;
                m0 = fmaxf(m0, x0); m1 = fmaxf(m1, x1);
            }
            float s0 = 0.f, s1 = 0.f;
#pragma unroll
            for (int s2 = 0; s2 < 9; s2++) {
                s0 += __expf(xs0[s2] - m0);
                s1 += __expf(xs1[s2] - m1);
            }
#pragma unroll
            for (int o = 1; o < 8; o <<= 1) {
                float om0 = __shfl_xor_sync(~0u, m0, o), os0 = __shfl_xor_sync(~0u, s0, o);
                float om1 = __shfl_xor_sync(~0u, m1, o), os1 = __shfl_xor_sync(~0u, s1, o);
                float nm0 = fmaxf(m0, om0);
                s0 = s0 * __expf(m0 - nm0) + os0 * __expf(om0 - nm0); m0 = nm0;
                float nm1 = fmaxf(m1, om1);
                s1 = s1 * __expf(m1 - nm1) + os1 * __expf(om1 - nm1); m1 = nm1;
            }
            if (lead) {
                gsh[0][row] = EPSV * (la - (m0 + __logf(s0)));
                gsh[1][row] = EPSV * (la - (m1 + __logf(s1)));
            }
        }
        __syncthreads();
    }

    // sum(P * C) for both chains
    float acc0 = 0.f, acc1 = 0.f;
    for (int idx = t; idx < 65 * 65; idx += 544) {
        int i = idx / 65, j = idx % 65;
        float c0 = Cm[0][i][j];
        float c1 = Cm[1][i][j];
        acc0 += __expf((fsh[0][i] + gsh[0][j] - c0) * INV_EPS) * c0;
        acc1 += __expf((fsh[1][i] + gsh[1][j] - c1) * INV_EPS) * c1;
    }
    for (int o = 16; o; o >>= 1) {
        acc0 += __shfl_xor_sync(~0u, acc0, o);
        acc1 += __shfl_xor_sync(~0u, acc1, o);
    }
    int lane = t & 31, warp = t >> 5;
    if (lane == 0) { rsum[0][warp] = acc0; rsum[1][warp] = acc1; }
    __syncthreads();
    if (t == 0) {
        float s0 = 0.f, s1 = 0.f;
        for (int w = 0; w < 17; w++) { s0 += rsum[0][w]; s1 += rsum[1][w]; }
        g_loss[blk * 2 + 0] = s0;   // (dgm0, Yb0) or (dgm0, Yn0)
        g_loss[blk * 2 + 1] = s1;   // (dgm1, Yb1) or (dgm1, Yn1)
    }
}

__global__ void final_kernel(float* out) {
    out[0] = 0.1f * (g_loss[0] + g_loss[1] + g_loss[2] + g_loss[3]);
}

// ---------------- launch ----------------
extern "C" void kernel_launch(void* const* d_in, const int* in_sizes, int n_in,
                              void* d_out, int out_size) {
    const float* adj = (const float*)d_in[0];
    const float* S = (const float*)d_in[1];
    gemm1_kernel<<<128, 256>>>(adj, S);
    gemm2_kernel<<<64, 256>>>(S);
    topo_kernel<<<1, 1024>>>();
    sinkhorn_kernel<<<2, 544>>>((const float*)d_in[2], (const float*)d_in[3],
                                (const float*)d_in[4], (const float*)d_in[5]);
    final_kernel<<<1, 1>>>((float*)d_out);
}

// round 11
// speedup vs baseline: 1.6094x; 1.6094x over previous
#include <cuda_runtime.h>
#include <cuda_bf16.h>
#include <math.h>
#include <stdint.h>

#define N_ 8192
#define K_ 64
#define CARDN 64
#define BIGF 1e9f
#define EPSV 0.01f
#define INV_EPS 100.0f
#define LOG64 4.1588830833596715f
#define SINK_ITERS 300

// ---------------- device scratch (no allocations allowed) ----------------
__device__ float g_T[N_ * K_];      // adj @ S   [8192,64]
__device__ float g_C[K_ * K_];      // S^T (adj S) [64,64]
__device__ float g_dgm0[CARDN * 2];
__device__ float g_dgm1[CARDN * 2];
__device__ float g_loss[4];

// =====================================================================
// GEMM1: T = adj @ S with mma.sync m16n8k8 tf32 (sm_80 path, valid on sm_103)
// grid 128, 128 threads (4 warps), CTA tile 64x64, warp tile 32x32, K-tile 32
// A smem row stride 36 floats (=4 mod 32 banks), B stride 72 (=8 mod 32):
// every scalar frag LDS is conflict-free; staging stores are STS.128.
// =====================================================================

__device__ __forceinline__ float tf32r(float x) {
    uint32_t o;
    asm("cvt.rna.tf32.f32 %0, %1;" : "=r"(o) : "f"(x));
    return __uint_as_float(o);
}

__device__ __forceinline__ void mma8(float* d, const uint32_t* a, uint32_t b0, uint32_t b1) {
    asm volatile(
        "mma.sync.aligned.m16n8k8.row.col.f32.tf32.tf32.f32 "
        "{%0,%1,%2,%3},{%4,%5,%6,%7},{%8,%9},{%0,%1,%2,%3};"
        : "+f"(d[0]), "+f"(d[1]), "+f"(d[2]), "+f"(d[3])
        : "r"(a[0]), "r"(a[1]), "r"(a[2]), "r"(a[3]), "r"(b0), "r"(b1));
}

#define ASTRIDE 36
#define BSTRIDE 72
#define GEMM1_SMEM ((64 * ASTRIDE + 32 * BSTRIDE) * 4)

__global__ void __launch_bounds__(128, 1) gemm1_tc(const float* __restrict__ A,
                                                   const float* __restrict__ S) {
    extern __shared__ float sm[];
    float* As = sm;                    // [64][36]
    float* Bs = sm + 64 * ASTRIDE;     // [32][72]

    int tid = threadIdx.x;
    int lane = tid & 31, w = tid >> 5;
    int wr = w >> 1, wc = w & 1;
    int g = lane >> 2, tig = lane & 3;
    int m0 = blockIdx.x * 64;

    // staging indices
    int rA = tid >> 3, c4A = tid & 7;      // A: rows rA + 16*i, float4 col c4A
    int kB = tid >> 4, cnB = tid & 15;     // B: rows kB + 8*i,  float4 col cnB

    const float* Ap = A + (size_t)(m0 + rA) * N_ + c4A * 4;
    const float* Bp = S + (size_t)kB * 64 + cnB * 4;

    float acc[2][4][4];
#pragma unroll
    for (int mc = 0; mc < 2; mc++)
#pragma unroll
        for (int j = 0; j < 4; j++)
#pragma unroll
            for (int e = 0; e < 4; e++) acc[mc][j][e] = 0.f;

    float4 aPre[4], bPre[4];
#pragma unroll
    for (int i = 0; i < 4; i++) {
        aPre[i] = *(const float4*)(Ap + (size_t)(16 * i) * N_);
        bPre[i] = *(const float4*)(Bp + (size_t)(8 * i) * 64);
    }
    // store tile 0 (with tf32 rounding)
#pragma unroll
    for (int i = 0; i < 4; i++) {
        float4 v = aPre[i];
        *(float4*)&As[(rA + 16 * i) * ASTRIDE + c4A * 4] =
            make_float4(tf32r(v.x), tf32r(v.y), tf32r(v.z), tf32r(v.w));
        float4 u = bPre[i];
        *(float4*)&Bs[(kB + 8 * i) * BSTRIDE + cnB * 4] =
            make_float4(tf32r(u.x), tf32r(u.y), tf32r(u.z), tf32r(u.w));
    }
    __syncthreads();

    for (int t = 0; t < 256; t++) {
        if (t < 255) {
            int k0n = (t + 1) * 32;
#pragma unroll
            for (int i = 0; i < 4; i++) {
                aPre[i] = *(const float4*)(Ap + (size_t)(16 * i) * N_ + k0n);
                bPre[i] = *(const float4*)(Bp + (size_t)(k0n + 8 * i) * 64);
            }
        }
        // compute from smem
#pragma unroll
        for (int kc = 0; kc < 4; kc++) {
            uint32_t af[2][4];
#pragma unroll
            for (int mc = 0; mc < 2; mc++) {
                const float* ab = As + (wr * 32 + mc * 16 + g) * ASTRIDE + kc * 8 + tig;
                af[mc][0] = __float_as_uint(ab[0]);
                af[mc][1] = __float_as_uint(ab[8 * ASTRIDE]);
                af[mc][2] = __float_as_uint(ab[4]);
                af[mc][3] = __float_as_uint(ab[8 * ASTRIDE + 4]);
            }
#pragma unroll
            for (int j = 0; j < 4; j++) {
                int nb = (wc * 4 + j) * 8 + g;
                const float* bb = Bs + (kc * 8 + tig) * BSTRIDE + nb;
                uint32_t b0 = __float_as_uint(bb[0]);
                uint32_t b1 = __float_as_uint(bb[4 * BSTRIDE]);
                mma8(acc[0][j], af[0], b0, b1);
                mma8(acc[1][j], af[1], b0, b1);
            }
        }
        __syncthreads();
        if (t < 255) {
#pragma unroll
            for (int i = 0; i < 4; i++) {
                float4 v = aPre[i];
                *(float4*)&As[(rA + 16 * i) * ASTRIDE + c4A * 4] =
                    make_float4(tf32r(v.x), tf32r(v.y), tf32r(v.z), tf32r(v.w));
                float4 u = bPre[i];
                *(float4*)&Bs[(kB + 8 * i) * BSTRIDE + cnB * 4] =
                    make_float4(tf32r(u.x), tf32r(u.y), tf32r(u.z), tf32r(u.w));
            }
            __syncthreads();
        }
    }

    // epilogue: D[mc][j] regs -> g_T
#pragma unroll
    for (int mc = 0; mc < 2; mc++)
#pragma unroll
        for (int j = 0; j < 4; j++) {
            int row = m0 + wr * 32 + mc * 16 + g;
            int col = wc * 32 + j * 8 + tig * 2;
            *(float2*)&g_T[(size_t)row * 64 + col] =
                make_float2(acc[mc][j][0], acc[mc][j][1]);
            *(float2*)&g_T[(size_t)(row + 8) * 64 + col] =
                make_float2(acc[mc][j][2], acc[mc][j][3]);
        }
}

// ================= GEMM2: C = S^T @ T  (64x8192 * 8192x64) =================
__global__ void __launch_bounds__(256) gemm2_kernel(const float* __restrict__ S) {
    int b = blockIdx.x;
    int tid = threadIdx.x;
    int j4 = (tid & 15) * 4;
    int slice = tid >> 4;
    float4 acc = make_float4(0.f, 0.f, 0.f, 0.f);
    for (int k = slice; k < N_; k += 16) {
        float sb = __ldg(S + (size_t)k * 64 + b);
        float4 tv = *(const float4*)&g_T[(size_t)k * 64 + j4];
        acc.x += sb * tv.x; acc.y += sb * tv.y;
        acc.z += sb * tv.z; acc.w += sb * tv.w;
    }
    __shared__ float4 red[256];
    red[tid] = acc;
    __syncthreads();
    if (tid < 64) {
        int g = tid >> 2, comp = tid & 3;
        float v = 0.f;
#pragma unroll
        for (int sl = 0; sl < 16; sl++)
            v += ((const float*)&red[sl * 16 + g])[comp];
        g_C[b * 64 + tid] = v;
    }
}

// ========== finalize D + Prim MST + dgm0 + triangle deaths + top-64 dgm1 ==========
__global__ void __launch_bounds__(1024) topo_kernel() {
    __shared__ float Dsm[64][65];
    __shared__ float pers[4096];
    __shared__ float wred[32];
    __shared__ float ws_s[63];
    __shared__ int us_s[63], vs_s[63];
    __shared__ float mind[64];
    __shared__ int minu[64];
    __shared__ unsigned long long msk[64];
    __shared__ float mx_s;
    __shared__ float bv_s[32];
    __shared__ int bi_s[32];

    int tid = threadIdx.x;
    int lane = tid & 31, warp = tid >> 5;

    float lmax = -1e30f;
#pragma unroll
    for (int w = 0; w < 4; w++) {
        int p = tid + w * 1024;
        int i = p >> 6, jj = p & 63;
        float cs = 0.5f * (g_C[i * 64 + jj] + g_C[jj * 64 + i]);
        Dsm[i][jj] = cs;
        lmax = fmaxf(lmax, cs);
    }
    for (int o = 16; o; o >>= 1) lmax = fmaxf(lmax, __shfl_xor_sync(~0u, lmax, o));
    if (lane == 0) wred[warp] = lmax;
    __syncthreads();
    if (warp == 0) {
        float v = wred[lane];
        for (int o = 16; o; o >>= 1) v = fmaxf(v, __shfl_xor_sync(~0u, v, o));
        if (lane == 0) mx_s = v;
    }
    __syncthreads();
    float inv = 1.0f / (mx_s + 1e-12f);
#pragma unroll
    for (int w = 0; w < 4; w++) {
        int p = tid + w * 1024;
        int i = p >> 6, jj = p & 63;
        float d = 1.0f - Dsm[i][jj] * inv;
        Dsm[i][jj] = (i == jj) ? 0.0f : d;
    }
    __syncthreads();

    if (warp == 0) {
        unsigned long long intree = 1ull;
#pragma unroll
        for (int h = 0; h < 2; h++) {
            int v = lane + 32 * h;
            mind[v] = Dsm[0][v];
            minu[v] = 0;
        }
        __syncwarp();
        for (int step = 0; step < 63; step++) {
            float bval = BIGF; int bidx = 64;
#pragma unroll
            for (int h = 0; h < 2; h++) {
                int v = lane + 32 * h;
                float mv = ((intree >> v) & 1ull) ? BIGF : mind[v];
                if (mv < bval || (mv == bval && v < bidx)) { bval = mv; bidx = v; }
            }
            for (int o = 16; o; o >>= 1) {
                float ov = __shfl_xor_sync(~0u, bval, o);
                int oi = __shfl_xor_sync(~0u, bidx, o);
                if (ov < bval || (ov == bval && oi < bidx)) { bval = ov; bidx = oi; }
            }
            int vstar = bidx;
            if (lane == 0) { ws_s[step] = bval; us_s[step] = minu[vstar]; vs_s[step] = vstar; }
            intree |= (1ull << vstar);
#pragma unroll
            for (int h = 0; h < 2; h++) {
                int v = lane + 32 * h;
                float dv = Dsm[vstar][v];
                if (dv < mind[v]) { mind[v] = dv; minu[v] = vstar; }
            }
            __syncwarp();
        }
    }
    __syncthreads();

    if (tid < 64) {
        g_dgm0[2 * tid] = 0.0f;
        g_dgm0[2 * tid + 1] = (tid < 63) ? ws_s[tid] : 0.0f;
        msk[tid] = 0ull;
    }
    __syncthreads();
    if (tid < 63) {
        atomicOr(&msk[us_s[tid]], 1ull << vs_s[tid]);
        atomicOr(&msk[vs_s[tid]], 1ull << us_s[tid]);
    }
    __syncthreads();

#pragma unroll
    for (int w = 0; w < 4; w++) {
        int p = tid + w * 1024;
        int i = p >> 6, jj = p & 63;
        float pe = -1.0f;
        if (i < jj && !((msk[i] >> jj) & 1ull)) {
            float mm = BIGF;
#pragma unroll
            for (int k = 0; k < 64; k++) {
                float t = fmaxf(Dsm[i][k], Dsm[jj][k]);
                if (k != i && k != jj) mm = fminf(mm, t);
            }
            float dij = Dsm[i][jj];
            pe = fmaxf(dij, mm) - dij;
        }
        pers[p] = pe;
    }
    __syncthreads();

    for (int r = 0; r < 64; r++) {
        float bval = -3e9f; int bidx = 1 << 30;
#pragma unroll
        for (int w = 0; w < 4; w++) {
            int p = tid + w * 1024;
            float v = pers[p];
            if (v > bval || (v == bval && p < bidx)) { bval = v; bidx = p; }
        }
        for (int o = 16; o; o >>= 1) {
            float ov = __shfl_xor_sync(~0u, bval, o);
            int oi = __shfl_xor_sync(~0u, bidx, o);
            if (ov > bval || (ov == bval && oi < bidx)) { bval = ov; bidx = oi; }
        }
        if (lane == 0) { bv_s[warp] = bval; bi_s[warp] = bidx; }
        __syncthreads();
        if (warp == 0) {
            float v2 = bv_s[lane]; int i2 = bi_s[lane];
            for (int o = 16; o; o >>= 1) {
                float ov = __shfl_xor_sync(~0u, v2, o);
                int oi = __shfl_xor_sync(~0u, i2, o);
                if (ov > v2 || (ov == v2 && oi < i2)) { v2 = ov; i2 = oi; }
            }
            if (lane == 0) {
                int i = i2 >> 6, jj = i2 & 63;
                float b = 0.f, d = 0.f;
                if (v2 > 0.f) { b = Dsm[i][jj]; d = b + v2; }
                g_dgm1[2 * r] = b;
                g_dgm1[2 * r + 1] = d;
                pers[i2] = -4e9f;
            }
        }
        __syncthreads();
    }
}

// ============ Sinkhorn W1: stabilized-by-own-potential (no max scan) ============
// tF_new = tF + la - log(sum_j exp(tF + G_j - Cs_ij)) == la - LSE_j(G_j - Cs_ij)
// (exactly the reference update in eps-scaled potentials). Row sums never
// underflow: the diagonal column keeps every sum >= e^-50.
__global__ void __launch_bounds__(544) sinkhorn_kernel(const float* __restrict__ Yb0,
                                                       const float* __restrict__ Yb1,
                                                       const float* __restrict__ Yn0,
                                                       const float* __restrict__ Yn1) {
    __shared__ float Cs[65][72];   // C * INV_EPS, cols 65..71 padded 1e30
    __shared__ float Ct[65][72];   // transpose, same padding
    __shared__ float Fsh[72], Gsh[72];
    __shared__ float rsum[17];

    int b = blockIdx.x;
    const float* X = (b & 1) ? g_dgm1 : g_dgm0;
    const float* Y = (b == 0) ? Yb0 : (b == 1) ? Yb1 : (b == 2) ? Yn0 : Yn1;
    int t = threadIdx.x;

    for (int idx = t; idx < 65 * 72; idx += 544) {
        int i = idx / 72, j = idx % 72;
        float v;
        if (j >= 65) v = 1e30f;
        else if (i < 64 && j < 64)
            v = fmaxf(fabsf(X[2 * i] - Y[2 * j]), fabsf(X[2 * i + 1] - Y[2 * j + 1])) * INV_EPS;
        else if (i < 64)
            v = 0.5f * (X[2 * i + 1] - X[2 * i]) * INV_EPS;
        else if (j < 64)
            v = 0.5f * (Y[2 * j + 1] - Y[2 * j]) * INV_EPS;
        else
            v = 0.f;
        Cs[i][j] = v;
    }
    if (t < 72) { Fsh[t] = 0.f; Gsh[t] = 0.f; }
    __syncthreads();
    for (int idx = t; idx < 65 * 72; idx += 544) {
        int i = idx / 72, j = idx % 72;
        Ct[i][j] = (j < 65) ? Cs[j][i] : 1e30f;
    }
    __syncthreads();

    int row = t >> 3; if (row > 64) row = 64;
    int sub = t & 7;
    bool lead = (t < 520) && (sub == 0);
    float la = (row == 64) ? LOG64 : 0.f;

    float csr[9], csc[9];
#pragma unroll
    for (int s2 = 0; s2 < 9; s2++) {
        int j = sub + 8 * s2;      // <= 71, in-bounds with padding
        csr[s2] = Cs[row][j];
        csc[s2] = Ct[row][j];
    }
    float tF = 0.f, tG = 0.f;

    for (int it = 0; it < SINK_ITERS; it++) {
        {
            float s = 0.f;
#pragma unroll
            for (int s2 = 0; s2 < 9; s2++)
                s += __expf(tF + Gsh[sub + 8 * s2] - csr[s2]);
#pragma unroll
            for (int o = 1; o < 8; o <<= 1) s += __shfl_xor_sync(~0u, s, o);
            tF += la - __logf(s);
            if (lead) Fsh[row] = tF;
        }
        __syncthreads();
        {
            float s = 0.f;
#pragma unroll
            for (int s2 = 0; s2 < 9; s2++)
                s += __expf(tG + Fsh[sub + 8 * s2] - csc[s2]);
#pragma unroll
            for (int o = 1; o < 8; o <<= 1) s += __shfl_xor_sync(~0u, s, o);
            tG += la - __logf(s);
            if (lead) Gsh[row] = tG;
        }
        __syncthreads();
    }

    // loss = sum P * C ; P = exp(tF_i + tG_j - Cs_ij), C = Cs * EPSV
    float acc = 0.f;
    if (t < 520) {
#pragma unroll
        for (int s2 = 0; s2 < 9; s2++) {
            float c = csr[s2];
            float p = __expf(tF + Gsh[sub + 8 * s2] - c);
            acc += p * c * EPSV;        // pads: exp(-1e30)=0 -> 0
        }
    }
    for (int o = 16; o; o >>= 1) acc += __shfl_xor_sync(~0u, acc, o);
    int lane = t & 31, warp = t >> 5;
    if (lane == 0) rsum[warp] = acc;
    __syncthreads();
    if (t == 0) {
        float s = 0.f;
        for (int w = 0; w < 17; w++) s += rsum[w];
        g_loss[b] = s;
    }
}

__global__ void final_kernel(float* out) {
    out[0] = 0.1f * (g_loss[0] + g_loss[1] + g_loss[2] + g_loss[3]);
}

// ---------------- launch ----------------
extern "C" void kernel_launch(void* const* d_in, const int* in_sizes, int n_in,
                              void* d_out, int out_size) {
    const float* adj = (const float*)d_in[0];
    const float* S = (const float*)d_in[1];
    cudaFuncSetAttribute(gemm1_tc, cudaFuncAttributeMaxDynamicSharedMemorySize, GEMM1_SMEM);
    gemm1_tc<<<128, 128, GEMM1_SMEM>>>(adj, S);
    gemm2_kernel<<<64, 256>>>(S);
    topo_kernel<<<1, 1024>>>();
    sinkhorn_kernel<<<4, 544>>>((const float*)d_in[2], (const float*)d_in[3],
                                (const float*)d_in[4], (const float*)d_in[5]);
    final_kernel<<<1, 1>>>((float*)d_out);
}

// round 13
// speedup vs baseline: 3.0056x; 1.8675x over previous
#include <cuda_runtime.h>
#include <cuda_bf16.h>
#include <math.h>
#include <stdint.h>

#define N_ 8192
#define K_ 64
#define CARDN 64
#define BIGF 1e9f
#define EPSV 0.01f
#define INV_EPS 100.0f
#define LOG64 4.1588830833596715f
#define SINK_ITERS 300

#define KSPLIT 8
#define KCHUNK (N_ / KSPLIT)        // 1024
#define KTILES (KCHUNK / 32)        // 32

// ---------------- device scratch (no allocations allowed) ----------------
__device__ float g_Tp[KSPLIT][N_ * K_];  // partial adj@S per K-chunk (16 MB)
__device__ float g_T[N_ * K_];           // adj @ S   [8192,64]
__device__ float g_C[K_ * K_];           // S^T (adj S) [64,64]
__device__ float g_dgm0[CARDN * 2];
__device__ float g_dgm1[CARDN * 2];
__device__ float g_loss[4];

// =====================================================================
// GEMM1: T = adj @ S with mma.sync m16n8k8 tf32, K-split for occupancy
// grid (128 m-tiles x 8 k-chunks), 128 threads; CTA tile 64x64, K-tile 32
// =====================================================================

__device__ __forceinline__ float tf32r(float x) {
    uint32_t o;
    asm("cvt.rna.tf32.f32 %0, %1;" : "=r"(o) : "f"(x));
    return __uint_as_float(o);
}

__device__ __forceinline__ void mma8(float* d, const uint32_t* a, uint32_t b0, uint32_t b1) {
    asm volatile(
        "mma.sync.aligned.m16n8k8.row.col.f32.tf32.tf32.f32 "
        "{%0,%1,%2,%3},{%4,%5,%6,%7},{%8,%9},{%0,%1,%2,%3};"
        : "+f"(d[0]), "+f"(d[1]), "+f"(d[2]), "+f"(d[3])
        : "r"(a[0]), "r"(a[1]), "r"(a[2]), "r"(a[3]), "r"(b0), "r"(b1));
}

#define ASTRIDE 36
#define BSTRIDE 72
#define GEMM1_SMEM ((64 * ASTRIDE + 32 * BSTRIDE) * 4)

__global__ void __launch_bounds__(128, 5) gemm1_tc(const float* __restrict__ A,
                                                   const float* __restrict__ S) {
    extern __shared__ float sm[];
    float* As = sm;                    // [64][36]
    float* Bs = sm + 64 * ASTRIDE;     // [32][72]

    int tid = threadIdx.x;
    int lane = tid & 31, w = tid >> 5;
    int wr = w >> 1, wc = w & 1;
    int g = lane >> 2, tig = lane & 3;
    int m0 = blockIdx.x * 64;
    int kbase = blockIdx.y * KCHUNK;

    // staging indices
    int rA = tid >> 3, c4A = tid & 7;      // A: rows rA + 16*i, float4 col c4A
    int kB = tid >> 4, cnB = tid & 15;     // B: rows kB + 8*i,  float4 col cnB

    const float* Ap = A + (size_t)(m0 + rA) * N_ + kbase + c4A * 4;
    const float* Bp = S + (size_t)(kbase + kB) * 64 + cnB * 4;

    float acc[2][4][4];
#pragma unroll
    for (int mc = 0; mc < 2; mc++)
#pragma unroll
        for (int j = 0; j < 4; j++)
#pragma unroll
            for (int e = 0; e < 4; e++) acc[mc][j][e] = 0.f;

    float4 aPre[4], bPre[4];
#pragma unroll
    for (int i = 0; i < 4; i++) {
        aPre[i] = *(const float4*)(Ap + (size_t)(16 * i) * N_);
        bPre[i] = *(const float4*)(Bp + (size_t)(8 * i) * 64);
    }
#pragma unroll
    for (int i = 0; i < 4; i++) {
        float4 v = aPre[i];
        *(float4*)&As[(rA + 16 * i) * ASTRIDE + c4A * 4] =
            make_float4(tf32r(v.x), tf32r(v.y), tf32r(v.z), tf32r(v.w));
        float4 u = bPre[i];
        *(float4*)&Bs[(kB + 8 * i) * BSTRIDE + cnB * 4] =
            make_float4(tf32r(u.x), tf32r(u.y), tf32r(u.z), tf32r(u.w));
    }
    __syncthreads();

    for (int t = 0; t < KTILES; t++) {
        if (t < KTILES - 1) {
            int k0n = (t + 1) * 32;
#pragma unroll
            for (int i = 0; i < 4; i++) {
                aPre[i] = *(const float4*)(Ap + (size_t)(16 * i) * N_ + k0n);
                bPre[i] = *(const float4*)(Bp + (size_t)(k0n + 8 * i) * 64);
            }
        }
#pragma unroll
        for (int kc = 0; kc < 4; kc++) {
            uint32_t af[2][4];
#pragma unroll
            for (int mc = 0; mc < 2; mc++) {
                const float* ab = As + (wr * 32 + mc * 16 + g) * ASTRIDE + kc * 8 + tig;
                af[mc][0] = __float_as_uint(ab[0]);
                af[mc][1] = __float_as_uint(ab[8 * ASTRIDE]);
                af[mc][2] = __float_as_uint(ab[4]);
                af[mc][3] = __float_as_uint(ab[8 * ASTRIDE + 4]);
            }
#pragma unroll
            for (int j = 0; j < 4; j++) {
                int nb = (wc * 4 + j) * 8 + g;
                const float* bb = Bs + (kc * 8 + tig) * BSTRIDE + nb;
                uint32_t b0 = __float_as_uint(bb[0]);
                uint32_t b1 = __float_as_uint(bb[4 * BSTRIDE]);
                mma8(acc[0][j], af[0], b0, b1);
                mma8(acc[1][j], af[1], b0, b1);
            }
        }
        __syncthreads();
        if (t < KTILES - 1) {
#pragma unroll
            for (int i = 0; i < 4; i++) {
                float4 v = aPre[i];
                *(float4*)&As[(rA + 16 * i) * ASTRIDE + c4A * 4] =
                    make_float4(tf32r(v.x), tf32r(v.y), tf32r(v.z), tf32r(v.w));
                float4 u = bPre[i];
                *(float4*)&Bs[(kB + 8 * i) * BSTRIDE + cnB * 4] =
                    make_float4(tf32r(u.x), tf32r(u.y), tf32r(u.z), tf32r(u.w));
            }
            __syncthreads();
        }
    }

    // epilogue: partial -> g_Tp[chunk]
    float* Tp = g_Tp[blockIdx.y];
#pragma unroll
    for (int mc = 0; mc < 2; mc++)
#pragma unroll
        for (int j = 0; j < 4; j++) {
            int row = m0 + wr * 32 + mc * 16 + g;
            int col = wc * 32 + j * 8 + tig * 2;
            *(float2*)&Tp[(size_t)row * 64 + col] =
                make_float2(acc[mc][j][0], acc[mc][j][1]);
            *(float2*)&Tp[(size_t)(row + 8) * 64 + col] =
                make_float2(acc[mc][j][2], acc[mc][j][3]);
        }
}

// reduce partials: g_T = sum_c g_Tp[c]
__global__ void __launch_bounds__(256) reduce_T() {
    int idx = (blockIdx.x * 256 + threadIdx.x) * 4;   // float4 index
    float4 s = *(const float4*)&g_Tp[0][idx];
#pragma unroll
    for (int c = 1; c < KSPLIT; c++) {
        float4 v = *(const float4*)&g_Tp[c][idx];
        s.x += v.x; s.y += v.y; s.z += v.z; s.w += v.w;
    }
    *(float4*)&g_T[idx] = s;
}

// ================= GEMM2: C = S^T @ T  (64x8192 * 8192x64) =================
__global__ void __launch_bounds__(256) gemm2_kernel(const float* __restrict__ S) {
    int b = blockIdx.x;
    int tid = threadIdx.x;
    int j4 = (tid & 15) * 4;
    int slice = tid >> 4;
    float4 acc = make_float4(0.f, 0.f, 0.f, 0.f);
    for (int k = slice; k < N_; k += 16) {
        float sb = __ldg(S + (size_t)k * 64 + b);
        float4 tv = *(const float4*)&g_T[(size_t)k * 64 + j4];
        acc.x += sb * tv.x; acc.y += sb * tv.y;
        acc.z += sb * tv.z; acc.w += sb * tv.w;
    }
    __shared__ float4 red[256];
    red[tid] = acc;
    __syncthreads();
    if (tid < 64) {
        int g = tid >> 2, comp = tid & 3;
        float v = 0.f;
#pragma unroll
        for (int sl = 0; sl < 16; sl++)
            v += ((const float*)&red[sl * 16 + g])[comp];
        g_C[b * 64 + tid] = v;
    }
}

// ========== finalize D + Prim MST + dgm0 + triangle deaths + top-64 dgm1 ==========
__global__ void __launch_bounds__(1024) topo_kernel() {
    __shared__ float Dsm[64][65];
    __shared__ float pers[4096];
    __shared__ float wred[32];
    __shared__ float ws_s[63];
    __shared__ int us_s[63], vs_s[63];
    __shared__ float mind[64];
    __shared__ int minu[64];
    __shared__ unsigned long long msk[64];
    __shared__ float mx_s;
    __shared__ float bv_s[32];
    __shared__ int bi_s[32];

    int tid = threadIdx.x;
    int lane = tid & 31, warp = tid >> 5;

    float lmax = -1e30f;
#pragma unroll
    for (int w = 0; w < 4; w++) {
        int p = tid + w * 1024;
        int i = p >> 6, jj = p & 63;
        float cs = 0.5f * (g_C[i * 64 + jj] + g_C[jj * 64 + i]);
        Dsm[i][jj] = cs;
        lmax = fmaxf(lmax, cs);
    }
    for (int o = 16; o; o >>= 1) lmax = fmaxf(lmax, __shfl_xor_sync(~0u, lmax, o));
    if (lane == 0) wred[warp] = lmax;
    __syncthreads();
    if (warp == 0) {
        float v = wred[lane];
        for (int o = 16; o; o >>= 1) v = fmaxf(v, __shfl_xor_sync(~0u, v, o));
        if (lane == 0) mx_s = v;
    }
    __syncthreads();
    float inv = 1.0f / (mx_s + 1e-12f);
#pragma unroll
    for (int w = 0; w < 4; w++) {
        int p = tid + w * 1024;
        int i = p >> 6, jj = p & 63;
        float d = 1.0f - Dsm[i][jj] * inv;
        Dsm[i][jj] = (i == jj) ? 0.0f : d;
    }
    __syncthreads();

    if (warp == 0) {
        unsigned long long intree = 1ull;
#pragma unroll
        for (int h = 0; h < 2; h++) {
            int v = lane + 32 * h;
            mind[v] = Dsm[0][v];
            minu[v] = 0;
        }
        __syncwarp();
        for (int step = 0; step < 63; step++) {
            float bval = BIGF; int bidx = 64;
#pragma unroll
            for (int h = 0; h < 2; h++) {
                int v = lane + 32 * h;
                float mv = ((intree >> v) & 1ull) ? BIGF : mind[v];
                if (mv < bval || (mv == bval && v < bidx)) { bval = mv; bidx = v; }
            }
            for (int o = 16; o; o >>= 1) {
                float ov = __shfl_xor_sync(~0u, bval, o);
                int oi = __shfl_xor_sync(~0u, bidx, o);
                if (ov < bval || (ov == bval && oi < bidx)) { bval = ov; bidx = oi; }
            }
            int vstar = bidx;
            if (lane == 0) { ws_s[step] = bval; us_s[step] = minu[vstar]; vs_s[step] = vstar; }
            intree |= (1ull << vstar);
#pragma unroll
            for (int h = 0; h < 2; h++) {
                int v = lane + 32 * h;
                float dv = Dsm[vstar][v];
                if (dv < mind[v]) { mind[v] = dv; minu[v] = vstar; }
            }
            __syncwarp();
        }
    }
    __syncthreads();

    if (tid < 64) {
        g_dgm0[2 * tid] = 0.0f;
        g_dgm0[2 * tid + 1] = (tid < 63) ? ws_s[tid] : 0.0f;
        msk[tid] = 0ull;
    }
    __syncthreads();
    if (tid < 63) {
        atomicOr(&msk[us_s[tid]], 1ull << vs_s[tid]);
        atomicOr(&msk[vs_s[tid]], 1ull << us_s[tid]);
    }
    __syncthreads();

#pragma unroll
    for (int w = 0; w < 4; w++) {
        int p = tid + w * 1024;
        int i = p >> 6, jj = p & 63;
        float pe = -1.0f;
        if (i < jj && !((msk[i] >> jj) & 1ull)) {
            float mm = BIGF;
#pragma unroll
            for (int k = 0; k < 64; k++) {
                float t = fmaxf(Dsm[i][k], Dsm[jj][k]);
                if (k != i && k != jj) mm = fminf(mm, t);
            }
            float dij = Dsm[i][jj];
            pe = fmaxf(dij, mm) - dij;
        }
        pers[p] = pe;
    }
    __syncthreads();

    for (int r = 0; r < 64; r++) {
        float bval = -3e9f; int bidx = 1 << 30;
#pragma unroll
        for (int w = 0; w < 4; w++) {
            int p = tid + w * 1024;
            float v = pers[p];
            if (v > bval || (v == bval && p < bidx)) { bval = v; bidx = p; }
        }
        for (int o = 16; o; o >>= 1) {
            float ov = __shfl_xor_sync(~0u, bval, o);
            int oi = __shfl_xor_sync(~0u, bidx, o);
            if (ov > bval || (ov == bval && oi < bidx)) { bval = ov; bidx = oi; }
        }
        if (lane == 0) { bv_s[warp] = bval; bi_s[warp] = bidx; }
        __syncthreads();
        if (warp == 0) {
            float v2 = bv_s[lane]; int i2 = bi_s[lane];
            for (int o = 16; o; o >>= 1) {
                float ov = __shfl_xor_sync(~0u, v2, o);
                int oi = __shfl_xor_sync(~0u, i2, o);
                if (ov > v2 || (ov == v2 && oi < i2)) { v2 = ov; i2 = oi; }
            }
            if (lane == 0) {
                int i = i2 >> 6, jj = i2 & 63;
                float b = 0.f, d = 0.f;
                if (v2 > 0.f) { b = Dsm[i][jj]; d = b + v2; }
                g_dgm1[2 * r] = b;
                g_dgm1[2 * r + 1] = d;
                pers[i2] = -4e9f;
            }
        }
        __syncthreads();
    }
}

// ============ Sinkhorn W1: stabilized-by-own-potential (no max scan) ============
__global__ void __launch_bounds__(544) sinkhorn_kernel(const float* __restrict__ Yb0,
                                                       const float* __restrict__ Yb1,
                                                       const float* __restrict__ Yn0,
                                                       const float* __restrict__ Yn1) {
    __shared__ float Cs[65][72];   // C * INV_EPS, cols 65..71 padded 1e30
    __shared__ float Ct[65][72];   // transpose, same padding
    __shared__ float Fsh[72], Gsh[72];
    __shared__ float rsum[17];

    int b = blockIdx.x;
    const float* X = (b & 1) ? g_dgm1 : g_dgm0;
    const float* Y = (b == 0) ? Yb0 : (b == 1) ? Yb1 : (b == 2) ? Yn0 : Yn1;
    int t = threadIdx.x;

    for (int idx = t; idx < 65 * 72; idx += 544) {
        int i = idx / 72, j = idx % 72;
        float v;
        if (j >= 65) v = 1e30f;
        else if (i < 64 && j < 64)
            v = fmaxf(fabsf(X[2 * i] - Y[2 * j]), fabsf(X[2 * i + 1] - Y[2 * j + 1])) * INV_EPS;
        else if (i < 64)
            v = 0.5f * (X[2 * i + 1] - X[2 * i]) * INV_EPS;
        else if (j < 64)
            v = 0.5f * (Y[2 * j + 1] - Y[2 * j]) * INV_EPS;
        else
            v = 0.f;
        Cs[i][j] = v;
    }
    if (t < 72) { Fsh[t] = 0.f; Gsh[t] = 0.f; }
    __syncthreads();
    for (int idx = t; idx < 65 * 72; idx += 544) {
        int i = idx / 72, j = idx % 72;
        Ct[i][j] = (j < 65) ? Cs[j][i] : 1e30f;
    }
    __syncthreads();

    int row = t >> 3; if (row > 64) row = 64;
    int sub = t & 7;
    bool lead = (t < 520) && (sub == 0);
    float la = (row == 64) ? LOG64 : 0.f;

    float csr[9], csc[9];
#pragma unroll
    for (int s2 = 0; s2 < 9; s2++) {
        int j = sub + 8 * s2;
        csr[s2] = Cs[row][j];
        csc[s2] = Ct[row][j];
    }
    float tF = 0.f, tG = 0.f;

    for (int it = 0; it < SINK_ITERS; it++) {
        {
            float s = 0.f;
#pragma unroll
            for (int s2 = 0; s2 < 9; s2++)
                s += __expf(tF + Gsh[sub + 8 * s2] - csr[s2]);
#pragma unroll
            for (int o = 1; o < 8; o <<= 1) s += __shfl_xor_sync(~0u, s, o);
            tF += la - __logf(s);
            if (lead) Fsh[row] = tF;
        }
        __syncthreads();
        {
            float s = 0.f;
#pragma unroll
            for (int s2 = 0; s2 < 9; s2++)
                s += __expf(tG + Fsh[sub + 8 * s2] - csc[s2]);
#pragma unroll
            for (int o = 1; o < 8; o <<= 1) s += __shfl_xor_sync(~0u, s, o);
            tG += la - __logf(s);
            if (lead) Gsh[row] = tG;
        }
        __syncthreads();
    }

    float acc = 0.f;
    if (t < 520) {
#pragma unroll
        for (int s2 = 0; s2 < 9; s2++) {
            float c = csr[s2];
            float p = __expf(tF + Gsh[sub + 8 * s2] - c);
            acc += p * c * EPSV;
        }
    }
    for (int o = 16; o; o >>= 1) acc += __shfl_xor_sync(~0u, acc, o);
    int lane = t & 31, warp = t >> 5;
    if (lane == 0) rsum[warp] = acc;
    __syncthreads();
    if (t == 0) {
        float s = 0.f;
        for (int w = 0; w < 17; w++) s += rsum[w];
        g_loss[b] = s;
    }
}

__global__ void final_kernel(float* out) {
    out[0] = 0.1f * (g_loss[0] + g_loss[1] + g_loss[2] + g_loss[3]);
}

// ---------------- launch ----------------
extern "C" void kernel_launch(void* const* d_in, const int* in_sizes, int n_in,
                              void* d_out, int out_size) {
    const float* adj = (const float*)d_in[0];
    const float* S = (const float*)d_in[1];
    cudaFuncSetAttribute(gemm1_tc, cudaFuncAttributeMaxDynamicSharedMemorySize, GEMM1_SMEM);
    dim3 g1grid(128, KSPLIT);
    gemm1_tc<<<g1grid, 128, GEMM1_SMEM>>>(adj, S);
    reduce_T<<<(N_ * K_ / 4) / 256, 256>>>();
    gemm2_kernel<<<64, 256>>>(S);
    topo_kernel<<<1, 1024>>>();
    sinkhorn_kernel<<<4, 544>>>((const float*)d_in[2], (const float*)d_in[3],
                                (const float*)d_in[4], (const float*)d_in[5]);
    final_kernel<<<1, 1>>>((float*)d_out);
}

// round 14
// speedup vs baseline: 3.7478x; 1.2470x over previous
#include <cuda_runtime.h>
#include <cuda_bf16.h>
#include <math.h>
#include <stdint.h>

#define N_ 8192
#define K_ 64
#define CARDN 64
#define BIGF 1e9f
#define EPSV 0.01f
#define INV_EPS 100.0f
#define LOG64 4.1588830833596715f
#define SINK_ITERS 300
#define LOG_ITERS 20
#define FOLD_EVERY 20

#define KSPLIT 8
#define KCHUNK (N_ / KSPLIT)        // 1024
#define KTILES (KCHUNK / 32)        // 32

// ---------------- device scratch (no allocations allowed) ----------------
__device__ float g_Tp[KSPLIT][N_ * K_];  // partial adj@S per K-chunk (16 MB)
__device__ float g_T[N_ * K_];           // adj @ S   [8192,64]
__device__ float g_C[K_ * K_];           // S^T (adj S) [64,64]
__device__ float g_dgm0[CARDN * 2];
__device__ float g_dgm1[CARDN * 2];
__device__ float g_loss[4];

// =====================================================================
// GEMM1: T = adj @ S with mma.sync m16n8k8 tf32, K-split for occupancy
// =====================================================================

__device__ __forceinline__ float tf32r(float x) {
    uint32_t o;
    asm("cvt.rna.tf32.f32 %0, %1;" : "=r"(o) : "f"(x));
    return __uint_as_float(o);
}

__device__ __forceinline__ void mma8(float* d, const uint32_t* a, uint32_t b0, uint32_t b1) {
    asm volatile(
        "mma.sync.aligned.m16n8k8.row.col.f32.tf32.tf32.f32 "
        "{%0,%1,%2,%3},{%4,%5,%6,%7},{%8,%9},{%0,%1,%2,%3};"
        : "+f"(d[0]), "+f"(d[1]), "+f"(d[2]), "+f"(d[3])
        : "r"(a[0]), "r"(a[1]), "r"(a[2]), "r"(a[3]), "r"(b0), "r"(b1));
}

#define ASTRIDE 36
#define BSTRIDE 72
#define GEMM1_SMEM ((64 * ASTRIDE + 32 * BSTRIDE) * 4)

__global__ void __launch_bounds__(128, 5) gemm1_tc(const float* __restrict__ A,
                                                   const float* __restrict__ S) {
    extern __shared__ float sm[];
    float* As = sm;                    // [64][36]
    float* Bs = sm + 64 * ASTRIDE;     // [32][72]

    int tid = threadIdx.x;
    int lane = tid & 31, w = tid >> 5;
    int wr = w >> 1, wc = w & 1;
    int g = lane >> 2, tig = lane & 3;
    int m0 = blockIdx.x * 64;
    int kbase = blockIdx.y * KCHUNK;

    int rA = tid >> 3, c4A = tid & 7;
    int kB = tid >> 4, cnB = tid & 15;

    const float* Ap = A + (size_t)(m0 + rA) * N_ + kbase + c4A * 4;
    const float* Bp = S + (size_t)(kbase + kB) * 64 + cnB * 4;

    float acc[2][4][4];
#pragma unroll
    for (int mc = 0; mc < 2; mc++)
#pragma unroll
        for (int j = 0; j < 4; j++)
#pragma unroll
            for (int e = 0; e < 4; e++) acc[mc][j][e] = 0.f;

    float4 aPre[4], bPre[4];
#pragma unroll
    for (int i = 0; i < 4; i++) {
        aPre[i] = *(const float4*)(Ap + (size_t)(16 * i) * N_);
        bPre[i] = *(const float4*)(Bp + (size_t)(8 * i) * 64);
    }
#pragma unroll
    for (int i = 0; i < 4; i++) {
        float4 v = aPre[i];
        *(float4*)&As[(rA + 16 * i) * ASTRIDE + c4A * 4] =
            make_float4(tf32r(v.x), tf32r(v.y), tf32r(v.z), tf32r(v.w));
        float4 u = bPre[i];
        *(float4*)&Bs[(kB + 8 * i) * BSTRIDE + cnB * 4] =
            make_float4(tf32r(u.x), tf32r(u.y), tf32r(u.z), tf32r(u.w));
    }
    __syncthreads();

    for (int t = 0; t < KTILES; t++) {
        if (t < KTILES - 1) {
            int k0n = (t + 1) * 32;
#pragma unroll
            for (int i = 0; i < 4; i++) {
                aPre[i] = *(const float4*)(Ap + (size_t)(16 * i) * N_ + k0n);
                bPre[i] = *(const float4*)(Bp + (size_t)(k0n + 8 * i) * 64);
            }
        }
#pragma unroll
        for (int kc = 0; kc < 4; kc++) {
            uint32_t af[2][4];
#pragma unroll
            for (int mc = 0; mc < 2; mc++) {
                const float* ab = As + (wr * 32 + mc * 16 + g) * ASTRIDE + kc * 8 + tig;
                af[mc][0] = __float_as_uint(ab[0]);
                af[mc][1] = __float_as_uint(ab[8 * ASTRIDE]);
                af[mc][2] = __float_as_uint(ab[4]);
                af[mc][3] = __float_as_uint(ab[8 * ASTRIDE + 4]);
            }
#pragma unroll
            for (int j = 0; j < 4; j++) {
                int nb = (wc * 4 + j) * 8 + g;
                const float* bb = Bs + (kc * 8 + tig) * BSTRIDE + nb;
                uint32_t b0 = __float_as_uint(bb[0]);
                uint32_t b1 = __float_as_uint(bb[4 * BSTRIDE]);
                mma8(acc[0][j], af[0], b0, b1);
                mma8(acc[1][j], af[1], b0, b1);
            }
        }
        __syncthreads();
        if (t < KTILES - 1) {
#pragma unroll
            for (int i = 0; i < 4; i++) {
                float4 v = aPre[i];
                *(float4*)&As[(rA + 16 * i) * ASTRIDE + c4A * 4] =
                    make_float4(tf32r(v.x), tf32r(v.y), tf32r(v.z), tf32r(v.w));
                float4 u = bPre[i];
                *(float4*)&Bs[(kB + 8 * i) * BSTRIDE + cnB * 4] =
                    make_float4(tf32r(u.x), tf32r(u.y), tf32r(u.z), tf32r(u.w));
            }
            __syncthreads();
        }
    }

    float* Tp = g_Tp[blockIdx.y];
#pragma unroll
    for (int mc = 0; mc < 2; mc++)
#pragma unroll
        for (int j = 0; j < 4; j++) {
            int row = m0 + wr * 32 + mc * 16 + g;
            int col = wc * 32 + j * 8 + tig * 2;
            *(float2*)&Tp[(size_t)row * 64 + col] =
                make_float2(acc[mc][j][0], acc[mc][j][1]);
            *(float2*)&Tp[(size_t)(row + 8) * 64 + col] =
                make_float2(acc[mc][j][2], acc[mc][j][3]);
        }
}

__global__ void __launch_bounds__(256) reduce_T() {
    int idx = (blockIdx.x * 256 + threadIdx.x) * 4;
    float4 s = *(const float4*)&g_Tp[0][idx];
#pragma unroll
    for (int c = 1; c < KSPLIT; c++) {
        float4 v = *(const float4*)&g_Tp[c][idx];
        s.x += v.x; s.y += v.y; s.z += v.z; s.w += v.w;
    }
    *(float4*)&g_T[idx] = s;
}

// ================= GEMM2: C = S^T @ T =================
__global__ void __launch_bounds__(256) gemm2_kernel(const float* __restrict__ S) {
    int b = blockIdx.x;
    int tid = threadIdx.x;
    int j4 = (tid & 15) * 4;
    int slice = tid >> 4;
    float4 acc = make_float4(0.f, 0.f, 0.f, 0.f);
    for (int k = slice; k < N_; k += 16) {
        float sb = __ldg(S + (size_t)k * 64 + b);
        float4 tv = *(const float4*)&g_T[(size_t)k * 64 + j4];
        acc.x += sb * tv.x; acc.y += sb * tv.y;
        acc.z += sb * tv.z; acc.w += sb * tv.w;
    }
    __shared__ float4 red[256];
    red[tid] = acc;
    __syncthreads();
    if (tid < 64) {
        int g = tid >> 2, comp = tid & 3;
        float v = 0.f;
#pragma unroll
        for (int sl = 0; sl < 16; sl++)
            v += ((const float*)&red[sl * 16 + g])[comp];
        g_C[b * 64 + tid] = v;
    }
}

// ========== finalize D + Prim MST + dgm0 + triangle deaths + top-64 dgm1 ==========
__global__ void __launch_bounds__(1024) topo_kernel() {
    __shared__ float Dsm[64][65];
    __shared__ float pers[4096];
    __shared__ float wred[32];
    __shared__ float ws_s[63];
    __shared__ int us_s[63], vs_s[63];
    __shared__ float mind[64];
    __shared__ int minu[64];
    __shared__ unsigned long long msk[64];
    __shared__ float mx_s;
    __shared__ float wmax[32];
    __shared__ int widx[32];

    int tid = threadIdx.x;
    int lane = tid & 31, warp = tid >> 5;

    float lmax = -1e30f;
#pragma unroll
    for (int w = 0; w < 4; w++) {
        int p = tid + w * 1024;
        int i = p >> 6, jj = p & 63;
        float cs = 0.5f * (g_C[i * 64 + jj] + g_C[jj * 64 + i]);
        Dsm[i][jj] = cs;
        lmax = fmaxf(lmax, cs);
    }
    for (int o = 16; o; o >>= 1) lmax = fmaxf(lmax, __shfl_xor_sync(~0u, lmax, o));
    if (lane == 0) wred[warp] = lmax;
    __syncthreads();
    if (warp == 0) {
        float v = wred[lane];
        for (int o = 16; o; o >>= 1) v = fmaxf(v, __shfl_xor_sync(~0u, v, o));
        if (lane == 0) mx_s = v;
    }
    __syncthreads();
    float inv = 1.0f / (mx_s + 1e-12f);
#pragma unroll
    for (int w = 0; w < 4; w++) {
        int p = tid + w * 1024;
        int i = p >> 6, jj = p & 63;
        float d = 1.0f - Dsm[i][jj] * inv;
        Dsm[i][jj] = (i == jj) ? 0.0f : d;
    }
    __syncthreads();

    if (warp == 0) {
        unsigned long long intree = 1ull;
#pragma unroll
        for (int h = 0; h < 2; h++) {
            int v = lane + 32 * h;
            mind[v] = Dsm[0][v];
            minu[v] = 0;
        }
        __syncwarp();
        for (int step = 0; step < 63; step++) {
            float bval = BIGF; int bidx = 64;
#pragma unroll
            for (int h = 0; h < 2; h++) {
                int v = lane + 32 * h;
                float mv = ((intree >> v) & 1ull) ? BIGF : mind[v];
                if (mv < bval || (mv == bval && v < bidx)) { bval = mv; bidx = v; }
            }
            for (int o = 16; o; o >>= 1) {
                float ov = __shfl_xor_sync(~0u, bval, o);
                int oi = __shfl_xor_sync(~0u, bidx, o);
                if (ov < bval || (ov == bval && oi < bidx)) { bval = ov; bidx = oi; }
            }
            int vstar = bidx;
            if (lane == 0) { ws_s[step] = bval; us_s[step] = minu[vstar]; vs_s[step] = vstar; }
            intree |= (1ull << vstar);
#pragma unroll
            for (int h = 0; h < 2; h++) {
                int v = lane + 32 * h;
                float dv = Dsm[vstar][v];
                if (dv < mind[v]) { mind[v] = dv; minu[v] = vstar; }
            }
            __syncwarp();
        }
    }
    __syncthreads();

    if (tid < 64) {
        g_dgm0[2 * tid] = 0.0f;
        g_dgm0[2 * tid + 1] = (tid < 63) ? ws_s[tid] : 0.0f;
        msk[tid] = 0ull;
    }
    __syncthreads();
    if (tid < 63) {
        atomicOr(&msk[us_s[tid]], 1ull << vs_s[tid]);
        atomicOr(&msk[vs_s[tid]], 1ull << us_s[tid]);
    }
    __syncthreads();

#pragma unroll
    for (int w = 0; w < 4; w++) {
        int p = tid + w * 1024;
        int i = p >> 6, jj = p & 63;
        float pe = -1.0f;
        if (i < jj && !((msk[i] >> jj) & 1ull)) {
            float mm = BIGF;
#pragma unroll
            for (int k = 0; k < 64; k++) {
                float t = fmaxf(Dsm[i][k], Dsm[jj][k]);
                if (k != i && k != jj) mm = fminf(mm, t);
            }
            float dij = Dsm[i][jj];
            pe = fmaxf(dij, mm) - dij;
        }
        pers[p] = pe;
    }
    __syncthreads();

    // per-warp segment maxima (warp w owns pers[w*128 .. w*128+127])
    {
        float bv = -3e9f; int bi = 1 << 30;
#pragma unroll
        for (int q = 0; q < 4; q++) {
            int p = warp * 128 + q * 32 + lane;
            float v = pers[p];
            if (v > bv || (v == bv && p < bi)) { bv = v; bi = p; }
        }
        for (int o = 16; o; o >>= 1) {
            float ov = __shfl_xor_sync(~0u, bv, o);
            int oi = __shfl_xor_sync(~0u, bi, o);
            if (ov > bv || (ov == bv && oi < bi)) { bv = ov; bi = oi; }
        }
        if (lane == 0) { wmax[warp] = bv; widx[warp] = bi; }
    }
    __syncthreads();

    // warp-0 tournament: 64 rounds, rescan only the winning segment
    if (warp == 0) {
        for (int r = 0; r < 64; r++) {
            float v2 = wmax[lane]; int i2 = widx[lane]; int sg = lane;
            for (int o = 16; o; o >>= 1) {
                float ov = __shfl_xor_sync(~0u, v2, o);
                int oi = __shfl_xor_sync(~0u, i2, o);
                int os = __shfl_xor_sync(~0u, sg, o);
                if (ov > v2 || (ov == v2 && oi < i2)) { v2 = ov; i2 = oi; sg = os; }
            }
            if (lane == 0) {
                int i = i2 >> 6, jj = i2 & 63;
                float b = 0.f, d = 0.f;
                if (v2 > 0.f) { b = Dsm[i][jj]; d = b + v2; }
                g_dgm1[2 * r] = b;
                g_dgm1[2 * r + 1] = d;
                pers[i2] = -4e9f;
            }
            __syncwarp();
            // rescan segment sg
            float nv = -3e9f; int ni = 1 << 30;
#pragma unroll
            for (int q = 0; q < 4; q++) {
                int p = sg * 128 + q * 32 + lane;
                float v = pers[p];
                if (v > nv || (v == nv && p < ni)) { nv = v; ni = p; }
            }
            for (int o = 16; o; o >>= 1) {
                float ov = __shfl_xor_sync(~0u, nv, o);
                int oi = __shfl_xor_sync(~0u, ni, o);
                if (ov > nv || (ov == nv && oi < ni)) { nv = ov; ni = oi; }
            }
            if (lane == 0) { wmax[sg] = nv; widx[sg] = ni; }
            __syncwarp();
        }
    }
}

// ============ Sinkhorn W1: 20 log-domain iters + 280 multiplicative iters ============
// After 20 stabilizing log-domain iterations, snapshot K_ij = exp(F0_i+G0_j-Cs_ij)
// into registers; then u_i = e^la / sum_j K_ij v_j etc. (exact same recursion),
// refolding K <- K*u*v every 20 iters to keep u,v in fp32 range.
__global__ void __launch_bounds__(544) sinkhorn_kernel(const float* __restrict__ Yb0,
                                                       const float* __restrict__ Yb1,
                                                       const float* __restrict__ Yn0,
                                                       const float* __restrict__ Yn1) {
    __shared__ float Cs[65][72];   // C * INV_EPS, cols 65..71 padded 1e30
    __shared__ float Ct[65][72];
    __shared__ float Fsh[72], Gsh[72];   // phase A: potentials; phase B: u, v
    __shared__ float rsum[17];

    int b = blockIdx.x;
    const float* X = (b & 1) ? g_dgm1 : g_dgm0;
    const float* Y = (b == 0) ? Yb0 : (b == 1) ? Yb1 : (b == 2) ? Yn0 : Yn1;
    int t = threadIdx.x;

    for (int idx = t; idx < 65 * 72; idx += 544) {
        int i = idx / 72, j = idx % 72;
        float v;
        if (j >= 65) v = 1e30f;
        else if (i < 64 && j < 64)
            v = fmaxf(fabsf(X[2 * i] - Y[2 * j]), fabsf(X[2 * i + 1] - Y[2 * j + 1])) * INV_EPS;
        else if (i < 64)
            v = 0.5f * (X[2 * i + 1] - X[2 * i]) * INV_EPS;
        else if (j < 64)
            v = 0.5f * (Y[2 * j + 1] - Y[2 * j]) * INV_EPS;
        else
            v = 0.f;
        Cs[i][j] = v;
    }
    if (t < 72) { Fsh[t] = 0.f; Gsh[t] = 0.f; }
    __syncthreads();
    for (int idx = t; idx < 65 * 72; idx += 544) {
        int i = idx / 72, j = idx % 72;
        Ct[i][j] = (j < 65) ? Cs[j][i] : 1e30f;
    }
    __syncthreads();

    int row = t >> 3; if (row > 64) row = 64;
    int sub = t & 7;
    bool lead = (t < 520) && (sub == 0);
    float la = (row == 64) ? LOG64 : 0.f;

    float csr[9], csc[9];
#pragma unroll
    for (int s2 = 0; s2 < 9; s2++) {
        int j = sub + 8 * s2;
        csr[s2] = Cs[row][j];
        csc[s2] = Ct[row][j];
    }
    float tF = 0.f, tG = 0.f;

    // ---- phase A: log-domain (stabilizing) ----
    for (int it = 0; it < LOG_ITERS; it++) {
        {
            float s = 0.f;
#pragma unroll
            for (int s2 = 0; s2 < 9; s2++)
                s += __expf(tF + Gsh[sub + 8 * s2] - csr[s2]);
#pragma unroll
            for (int o = 1; o < 8; o <<= 1) s += __shfl_xor_sync(~0u, s, o);
            tF += la - __logf(s);
            if (lead) Fsh[row] = tF;
        }
        __syncthreads();
        {
            float s = 0.f;
#pragma unroll
            for (int s2 = 0; s2 < 9; s2++)
                s += __expf(tG + Fsh[sub + 8 * s2] - csc[s2]);
#pragma unroll
            for (int o = 1; o < 8; o <<= 1) s += __shfl_xor_sync(~0u, s, o);
            tG += la - __logf(s);
            if (lead) Gsh[row] = tG;
        }
        __syncthreads();
    }

    // ---- snapshot K into registers ----
    float kr[9], kc[9];
#pragma unroll
    for (int s2 = 0; s2 < 9; s2++) {
        kr[s2] = __expf(tF + Gsh[sub + 8 * s2] - csr[s2]);   // pads -> exp(-1e30)=0
        kc[s2] = __expf(tG + Fsh[sub + 8 * s2] - csc[s2]);
    }
    __syncthreads();
    if (t < 72) { Fsh[t] = 1.f; Gsh[t] = 1.f; }   // now u, v
    __syncthreads();

    float ela = (row == 64) ? 64.f : 1.f;

    // ---- phase B: multiplicative ----
    for (int it = LOG_ITERS; it < SINK_ITERS; it++) {
        {
            float s = 0.f;
#pragma unroll
            for (int s2 = 0; s2 < 9; s2++)
                s += kr[s2] * Gsh[sub + 8 * s2];
#pragma unroll
            for (int o = 1; o < 8; o <<= 1) s += __shfl_xor_sync(~0u, s, o);
            if (lead) Fsh[row] = ela / s;
        }
        __syncthreads();
        {
            float s = 0.f;
#pragma unroll
            for (int s2 = 0; s2 < 9; s2++)
                s += kc[s2] * Fsh[sub + 8 * s2];
#pragma unroll
            for (int o = 1; o < 8; o <<= 1) s += __shfl_xor_sync(~0u, s, o);
            if (lead) Gsh[row] = ela / s;
        }
        __syncthreads();
        if (((it + 1) % FOLD_EVERY) == 0 && it != SINK_ITERS - 1) {
            float ur = Fsh[row], vr = Gsh[row];
#pragma unroll
            for (int s2 = 0; s2 < 9; s2++) {
                kr[s2] *= ur * Gsh[sub + 8 * s2];
                kc[s2] *= vr * Fsh[sub + 8 * s2];
            }
            __syncthreads();
            if (t < 72) { Fsh[t] = 1.f; Gsh[t] = 1.f; }
            __syncthreads();
        }
    }

    // loss = sum P*C ; P_ij = kr * u_i * v_j, C = csr * EPSV
    float acc = 0.f;
    if (t < 520) {
        float ur = Fsh[row];
#pragma unroll
        for (int s2 = 0; s2 < 9; s2++) {
            float c = csr[s2];
            acc += kr[s2] * ur * Gsh[sub + 8 * s2] * c * EPSV;
        }
    }
    for (int o = 16; o; o >>= 1) acc += __shfl_xor_sync(~0u, acc, o);
    int lane = t & 31, warp = t >> 5;
    if (lane == 0) rsum[warp] = acc;
    __syncthreads();
    if (t == 0) {
        float s = 0.f;
        for (int w = 0; w < 17; w++) s += rsum[w];
        g_loss[b] = s;
    }
}

__global__ void final_kernel(float* out) {
    out[0] = 0.1f * (g_loss[0] + g_loss[1] + g_loss[2] + g_loss[3]);
}

// ---------------- launch ----------------
extern "C" void kernel_launch(void* const* d_in, const int* in_sizes, int n_in,
                              void* d_out, int out_size) {
    const float* adj = (const float*)d_in[0];
    const float* S = (const float*)d_in[1];
    cudaFuncSetAttribute(gemm1_tc, cudaFuncAttributeMaxDynamicSharedMemorySize, GEMM1_SMEM);
    dim3 g1grid(128, KSPLIT);
    gemm1_tc<<<g1grid, 128, GEMM1_SMEM>>>(adj, S);
    reduce_T<<<(N_ * K_ / 4) / 256, 256>>>();
    gemm2_kernel<<<64, 256>>>(S);
    topo_kernel<<<1, 1024>>>();
    sinkhorn_kernel<<<4, 544>>>((const float*)d_in[2], (const float*)d_in[3],
                                (const float*)d_in[4], (const float*)d_in[5]);
    final_kernel<<<1, 1>>>((float*)d_out);
}